// round 11
// baseline (speedup 1.0000x reference)
#include <cuda_runtime.h>
#include <cuda_fp16.h>

#define THREADS 1024
#define RPB     8
#define NCTA    128
#define SEQ     1024
#define GATES   512
#define HID     128

// ---- smem ----
#define B_STRIDE  80        // bytes per lane row: 8 kt * 8B + 16 pad (conflict-free LDS.128)
#define B_BUF     2560      // 32 lanes * 80
#define B_OFF     0         // double buffered: 2 * 2560
#define RED_OFF   5120      // output reduction 128*8 f32
#define SMEM_TOTAL 9216

typedef unsigned int u32;

// f32-accumulator HMMA
static __device__ __forceinline__ void mma_f32(float* d, const uint4& a, u32 b0, u32 b1) {
    asm volatile("mma.sync.aligned.m16n8k16.row.col.f32.f16.f16.f32 "
        "{%0,%1,%2,%3}, {%4,%5,%6,%7}, {%8,%9}, {%0,%1,%2,%3};"
        : "+f"(d[0]), "+f"(d[1]), "+f"(d[2]), "+f"(d[3])
        : "r"(a.x), "r"(a.y), "r"(a.z), "r"(a.w), "r"(b0), "r"(b1));
}
static __device__ __forceinline__ u32 tanh2u(u32 v) {
    u32 r; asm("tanh.approx.f16x2 %0, %1;" : "=r"(r) : "r"(v)); return r;
}
static __device__ __forceinline__ u32 packf2(float lo, float hi) {   // lo -> low half
    u32 r; asm("cvt.rn.f16x2.f32 %0, %1, %2;" : "=r"(r) : "f"(hi), "f"(lo)); return r;
}
static __device__ __forceinline__ u32 pack_h2(float a, float b) {
    __half2 h = __halves2half2(__float2half_rn(a), __float2half_rn(b));
    return *reinterpret_cast<u32*>(&h);
}
static __device__ __forceinline__ __half2 asH2(u32 v) { return *reinterpret_cast<__half2*>(&v); }
static __device__ __forceinline__ u32 asU32(__half2 v) { return *reinterpret_cast<u32*>(&v); }

__global__ void __launch_bounds__(THREADS, 1)
lstm_w32b_kernel(const float* __restrict__ x,  const float* __restrict__ Wi,
                 const float* __restrict__ Wh, const float* __restrict__ b,
                 const float* __restrict__ Wd, const float* __restrict__ bd,
                 float* __restrict__ out)
{
    extern __shared__ char smem[];
    const int tid  = threadIdx.x;
    const int w    = tid >> 5;           // warp 0..31: hid set 4w..4w+3
    const int lane = tid & 31;
    const int g    = lane >> 2;          // 0..7
    const int q    = lane & 3;           // batch cols 2q, 2q+1
    const bool upd = (g >= 4);           // upper half-lanes own g,o gates + update
    const int r0   = blockIdx.x * RPB;
    const int p    = 4 * w + (g & 3);    // my hid

    // m-tile rows: jA = i (lower) / g-gate (upper); jB = jA + 128 = f / o.
    const int jA = ((g >> 2) << 8) + p;          // g<4: p (i) ; g>=4: 256+p (g)
    const int jB = jA + 128;                     // f / o
    const float scA = upd ? 1.0f : 0.5f;         // g-gate unscaled; sigmoids 0.5x
    const float scB = 0.5f;

    // ---- A = Wh^T fp16 fragments -> registers (sigmoid rows pre-scaled) ----
    uint4 areg[8];
#pragma unroll
    for (int kt = 0; kt < 8; kt++) {
        int c0 = kt * 16 + 2 * q, c2 = c0 + 8;
        areg[kt].x = pack_h2(scA * Wh[c0 * GATES + jA], scA * Wh[(c0 + 1) * GATES + jA]);
        areg[kt].y = pack_h2(scB * Wh[c0 * GATES + jB], scB * Wh[(c0 + 1) * GATES + jB]);
        areg[kt].z = pack_h2(scA * Wh[c2 * GATES + jA], scA * Wh[(c2 + 1) * GATES + jA]);
        areg[kt].w = pack_h2(scB * Wh[c2 * GATES + jB], scB * Wh[(c2 + 1) * GATES + jB]);
    }
    const float wiA = scA * Wi[jA], bA = scA * b[jA];
    const float wiB = scB * Wi[jB], bB = scB * b[jB];
    // activation fixup: act = tanh_out * s + c  (sigmoid: 0.5,0.5 ; tanh: 1,0)
    const __half2 sA2 = asH2(pack_h2(upd ? 1.f : 0.5f, upd ? 1.f : 0.5f));
    const __half2 cA2 = asH2(pack_h2(upd ? 0.f : 0.5f, upd ? 0.f : 0.5f));
    const __half2 h05 = asH2(pack_h2(0.5f, 0.5f));

    // B-frag writer offsets (verified layout): (k=p, col=r) ->
    // lane_t = r*4 + ((p&7)>>1); byte = lane_t*80 + (p>>4)*8 + ((p&15)>=8?4:0) + (p&1)*2
    const int off0 = ((2 * q) * 4 + ((p & 7) >> 1)) * B_STRIDE
                   + (p >> 4) * 8 + (((p & 15) >= 8) ? 4 : 0) + (p & 1) * 2;
    const int off1 = off0 + 4 * B_STRIDE;        // col 2q+1

    // zero both B buffers (h0 = 0)
    for (int i = tid; i < (2 * B_BUF) / 4; i += THREADS)
        *reinterpret_cast<u32*>(smem + B_OFF + i * 4) = 0;

    // x stream for my 2 batch rows (broadcast LDG, L1-resident)
    const float* xr = x + (r0 + 2 * q) * SEQ;    // row 2q; row 2q+1 at +SEQ
    float x0c = xr[0], x1c = xr[SEQ];

    __half2 c2v = asH2(0u);
    __half2 h2v = asH2(0u);

    __syncthreads();

    // ============ sequential loop: ONE barrier per step ============
#pragma unroll 2
    for (int s = 0; s < SEQ; s++) {
        int sn = (s + 1 < SEQ) ? s + 1 : s;
        float x0n = xr[sn], x1n = xr[SEQ + sn];

        const char* Bc = smem + B_OFF + (s & 1) * B_BUF + lane * B_STRIDE;
        float d1[4] = {bA, bA, bB, bB};          // even-kt chain (bias folded)
        float d2[4] = {0.f, 0.f, 0.f, 0.f};     // odd-kt chain
#pragma unroll
        for (int i = 0; i < 4; i++) {
            uint4 bv = *reinterpret_cast<const uint4*>(Bc + i * 16);   // kt 2i, 2i+1
            mma_f32(d1, areg[2 * i],     bv.x, bv.y);
            mma_f32(d2, areg[2 * i + 1], bv.z, bv.w);
        }

        // ---- epilogue ----
        float v0 = fmaf(x0c, wiA, d1[0] + d2[0]);
        float v1 = fmaf(x1c, wiA, d1[1] + d2[1]);
        float v2 = fmaf(x0c, wiB, d1[2] + d2[2]);
        float v3 = fmaf(x1c, wiB, d1[3] + d2[3]);
        __half2 aAct = __hfma2(asH2(tanh2u(packf2(v0, v1))), sA2, cA2);  // i (lo) / g (up)
        __half2 bAct = __hfma2(asH2(tanh2u(packf2(v2, v3))), h05, h05);  // f / o

        // ---- exchange: upper receives i2, f2 from paired lower lane ----
        u32 i2r = __shfl_xor_sync(0xffffffffu, asU32(aAct), 16);
        u32 f2r = __shfl_xor_sync(0xffffffffu, asU32(bAct), 16);

        char* Bn = smem + B_OFF + ((s + 1) & 1) * B_BUF;
        if (upd) {
            __half2 ig2 = __hmul2(asH2(i2r), aAct);       // i * g
            c2v = __hfma2(asH2(f2r), c2v, ig2);           // c = f*c + i*g   (f16x2)
            h2v = __hmul2(bAct, asH2(tanh2u(asU32(c2v)))); // h = o * tanh(c)
            *reinterpret_cast<unsigned short*>(Bn + off0) = __half_as_ushort(__low2half(h2v));
            *reinterpret_cast<unsigned short*>(Bn + off1) = __half_as_ushort(__high2half(h2v));
        }
        x0c = x0n; x1c = x1n;

        __syncthreads();   // B[nxt] published; B[cur] reads all complete
    }

    // ============ output: out[r] = h . Wd + bd ============
    float* red = reinterpret_cast<float*>(smem + RED_OFF);
    if (upd) {
        float wd = Wd[p];
        red[p * 8 + 2 * q]     = __low2float(h2v) * wd;
        red[p * 8 + 2 * q + 1] = __high2float(h2v) * wd;
    }
    __syncthreads();
    if (tid < RPB) {
        float sum = 0.f;
        for (int pp = 0; pp < HID; pp++) sum += red[pp * 8 + tid];
        out[r0 + tid] = sum + bd[0];
    }
}

extern "C" void kernel_launch(void* const* d_in, const int* in_sizes, int n_in,
                              void* d_out, int out_size)
{
    (void)in_sizes; (void)n_in; (void)out_size;
    const float* x  = (const float*)d_in[0];
    const float* Wi = (const float*)d_in[1];
    const float* Wh = (const float*)d_in[2];
    const float* b  = (const float*)d_in[3];
    const float* Wd = (const float*)d_in[4];
    const float* bd = (const float*)d_in[5];
    float* out = (float*)d_out;

    cudaFuncSetAttribute(lstm_w32b_kernel,
                         cudaFuncAttributeMaxDynamicSharedMemorySize, SMEM_TOTAL);
    lstm_w32b_kernel<<<NCTA, THREADS, SMEM_TOTAL>>>(x, Wi, Wh, b, Wd, bd, out);
}

// round 12
// speedup vs baseline: 1.5314x; 1.5314x over previous
#include <cuda_runtime.h>
#include <cuda_fp16.h>

#define THREADS 512
#define RPB     8
#define NCTA    128
#define SEQ     1024
#define GATES   512
#define HID     128

// ---- smem ----
#define B_STRIDE  80        // bytes/lane row (8 kt * 8B + pad, conflict-free LDS.128)
#define B_BUF     2560
#define B_OFF     0         // double buffered
#define RED_OFF   5120      // 128*8 f32
#define SMEM_TOTAL 9216

typedef unsigned int u32;

static __device__ __forceinline__ void mma_f32(float* d, const uint4& a, u32 b0, u32 b1) {
    asm volatile("mma.sync.aligned.m16n8k16.row.col.f32.f16.f16.f32 "
        "{%0,%1,%2,%3}, {%4,%5,%6,%7}, {%8,%9}, {%0,%1,%2,%3};"
        : "+f"(d[0]), "+f"(d[1]), "+f"(d[2]), "+f"(d[3])
        : "r"(a.x), "r"(a.y), "r"(a.z), "r"(a.w), "r"(b0), "r"(b1));
}
static __device__ __forceinline__ float tanhap(float x) {
    float r; asm("tanh.approx.f32 %0, %1;" : "=f"(r) : "f"(x)); return r;
}
static __device__ __forceinline__ u32 tanh2u(u32 v) {
    u32 r; asm("tanh.approx.f16x2 %0, %1;" : "=r"(r) : "r"(v)); return r;
}
static __device__ __forceinline__ u32 packf2(float lo, float hi) {   // lo -> low half
    u32 r; asm("cvt.rn.f16x2.f32 %0, %1, %2;" : "=r"(r) : "f"(hi), "f"(lo)); return r;
}
static __device__ __forceinline__ u32 pack_h2(float a, float b) {
    __half2 h = __halves2half2(__float2half_rn(a), __float2half_rn(b));
    return *reinterpret_cast<u32*>(&h);
}
static __device__ __forceinline__ __half2 asH2(u32 v) { return *reinterpret_cast<__half2*>(&v); }
static __device__ __forceinline__ u32 asU32(__half2 v) { return *reinterpret_cast<u32*>(&v); }

__global__ void __launch_bounds__(THREADS, 1)
lstm_mx_kernel(const float* __restrict__ x,  const float* __restrict__ Wi,
               const float* __restrict__ Wh, const float* __restrict__ b,
               const float* __restrict__ Wd, const float* __restrict__ bd,
               float* __restrict__ out)
{
    extern __shared__ char smem[];
    const int tid  = threadIdx.x;
    const int w    = tid >> 5;           // warp 0..15: hid set 8w..8w+7
    const int lane = tid & 31;
    const int g    = lane >> 2;          // hid p = 8w+g
    const int q    = lane & 3;           // batch cols 2q, 2q+1
    const int r0   = blockIdx.x * RPB;
    const int p    = 8 * w + g;

    // m-tiles: mt0 rows = i (j=p, x0.5) | f (j=128+p, x0.5)
    //          mt1 rows = g (j=256+p, x1) | o (j=384+p, x0.5)
    const int jI = p, jF = 128 + p, jG = 256 + p, jO = 384 + p;

    // ---- A = Wh^T fp16 fragments -> registers ----
    uint4 areg[2][8];
#pragma unroll
    for (int kt = 0; kt < 8; kt++) {
        int c0 = kt * 16 + 2 * q, c2 = c0 + 8;
        areg[0][kt].x = pack_h2(0.5f * Wh[c0 * GATES + jI], 0.5f * Wh[(c0 + 1) * GATES + jI]);
        areg[0][kt].y = pack_h2(0.5f * Wh[c0 * GATES + jF], 0.5f * Wh[(c0 + 1) * GATES + jF]);
        areg[0][kt].z = pack_h2(0.5f * Wh[c2 * GATES + jI], 0.5f * Wh[(c2 + 1) * GATES + jI]);
        areg[0][kt].w = pack_h2(0.5f * Wh[c2 * GATES + jF], 0.5f * Wh[(c2 + 1) * GATES + jF]);
        areg[1][kt].x = pack_h2(Wh[c0 * GATES + jG],        Wh[(c0 + 1) * GATES + jG]);
        areg[1][kt].y = pack_h2(0.5f * Wh[c0 * GATES + jO], 0.5f * Wh[(c0 + 1) * GATES + jO]);
        areg[1][kt].z = pack_h2(Wh[c2 * GATES + jG],        Wh[(c2 + 1) * GATES + jG]);
        areg[1][kt].w = pack_h2(0.5f * Wh[c2 * GATES + jO], 0.5f * Wh[(c2 + 1) * GATES + jO]);
    }
    const float bI = 0.5f * b[jI], bF = 0.5f * b[jF], bG = b[jG], bO = 0.5f * b[jO];
    const float wiI = 0.5f * Wi[jI], wiF = 0.5f * Wi[jF], wiG = Wi[jG], wiO = 0.5f * Wi[jO];
    const __half2 hHALF = asH2(pack_h2(0.5f, 0.5f));

    // B-frag writer offsets (R10-verified layout)
    const int off0 = ((2 * q) * 4 + ((p & 7) >> 1)) * B_STRIDE
                   + (p >> 4) * 8 + (((p & 15) >= 8) ? 4 : 0) + (p & 1) * 2;
    const int off1 = off0 + 4 * B_STRIDE;

    // zero both B buffers (h0 = 0)
    for (int i = tid; i < (2 * B_BUF) / 4; i += THREADS)
        *reinterpret_cast<u32*>(smem + B_OFF + i * 4) = 0;

    const float* xr = x + (r0 + 2 * q) * SEQ;    // row 2q; row 2q+1 at +SEQ
    float x0c = xr[0], x1c = xr[SEQ];

    float c0s = 0.f, c1s = 0.f;
    __half2 h2v = asH2(0u);

    __syncthreads();

    // ============ sequential loop: ONE barrier per step ============
#pragma unroll 2
    for (int s = 0; s < SEQ; s++) {
        int sn = (s + 1 < SEQ) ? s + 1 : s;
        float x0n = xr[sn], x1n = xr[SEQ + sn];

        // d1 = bias-init chain (even kt); d2 = x*Wi-init chain (odd kt)
        float d1a[4] = {bI, bI, bF, bF};
        float d2a[4] = {x0c * wiI, x1c * wiI, x0c * wiF, x1c * wiF};
        float d1b[4] = {bG, bG, bO, bO};
        float d2b[4] = {x0c * wiG, x1c * wiG, x0c * wiO, x1c * wiO};

        const char* Bc = smem + B_OFF + (s & 1) * B_BUF + lane * B_STRIDE;
#pragma unroll
        for (int i = 0; i < 4; i++) {
            uint4 bv = *reinterpret_cast<const uint4*>(Bc + i * 16);   // kt 2i, 2i+1
            mma_f32(d1a, areg[0][2 * i],     bv.x, bv.y);
            mma_f32(d1b, areg[1][2 * i],     bv.x, bv.y);
            mma_f32(d2a, areg[0][2 * i + 1], bv.z, bv.w);
            mma_f32(d2b, areg[1][2 * i + 1], bv.z, bv.w);
        }

        // ---- activations: i,f,g scalar f32 (integrate into c); o f16x2 ----
        float tI0 = tanhap(d1a[0] + d2a[0]);
        float tI1 = tanhap(d1a[1] + d2a[1]);
        float tF0 = tanhap(d1a[2] + d2a[2]);
        float tF1 = tanhap(d1a[3] + d2a[3]);
        float tG0 = tanhap(d1b[0] + d2b[0]);
        float tG1 = tanhap(d1b[1] + d2b[1]);
        u32 to2 = tanh2u(packf2(d1b[2] + d2b[2], d1b[3] + d2b[3]));

        // ---- update: c = 0.5*( fma(tF,c,c) + fma(tI,tG,tG) )  [fp32] ----
        float F0 = fmaf(tF0, c0s, c0s);
        float I0 = fmaf(tI0, tG0, tG0);
        float F1 = fmaf(tF1, c1s, c1s);
        float I1 = fmaf(tI1, tG1, tG1);
        c0s = 0.5f * (F0 + I0);
        c1s = 0.5f * (F1 + I1);

        // h = o * tanh(c) = fma2(t_o, 0.5*tc, 0.5*tc)
        __half2 tch = __hmul2(asH2(tanh2u(packf2(c0s, c1s))), hHALF);
        h2v = __hfma2(asH2(to2), tch, tch);

        char* Bn = smem + B_OFF + ((s + 1) & 1) * B_BUF;
        *reinterpret_cast<unsigned short*>(Bn + off0) = __half_as_ushort(__low2half(h2v));
        *reinterpret_cast<unsigned short*>(Bn + off1) = __half_as_ushort(__high2half(h2v));

        x0c = x0n; x1c = x1n;

        __syncthreads();   // B[nxt] published; B[cur] reads complete
    }

    // ============ output: out[r] = h . Wd + bd ============
    float* red = reinterpret_cast<float*>(smem + RED_OFF);
    {
        float wd = Wd[p];
        red[p * 8 + 2 * q]     = __low2float(h2v) * wd;
        red[p * 8 + 2 * q + 1] = __high2float(h2v) * wd;
    }
    __syncthreads();
    if (tid < RPB) {
        float sum = 0.f;
        for (int pp = 0; pp < HID; pp++) sum += red[pp * 8 + tid];
        out[r0 + tid] = sum + bd[0];
    }
}

extern "C" void kernel_launch(void* const* d_in, const int* in_sizes, int n_in,
                              void* d_out, int out_size)
{
    (void)in_sizes; (void)n_in; (void)out_size;
    const float* x  = (const float*)d_in[0];
    const float* Wi = (const float*)d_in[1];
    const float* Wh = (const float*)d_in[2];
    const float* b  = (const float*)d_in[3];
    const float* Wd = (const float*)d_in[4];
    const float* bd = (const float*)d_in[5];
    float* out = (float*)d_out;

    cudaFuncSetAttribute(lstm_mx_kernel,
                         cudaFuncAttributeMaxDynamicSharedMemorySize, SMEM_TOTAL);
    lstm_mx_kernel<<<NCTA, THREADS, SMEM_TOTAL>>>(x, Wi, Wh, b, Wd, bd, out);
}